// round 15
// baseline (speedup 1.0000x reference)
#include <cuda_runtime.h>
#include <cuda_bf16.h>
#include <cstdint>

#define B_   2
#define T_   4096
#define D_   2048
#define H_   16
#define HD_  128
#define CH_  256
#define NCH_ 16
#define BT_  (B_*T_)
#define SCALE_ 0.08838834764831845f

// ---------------- scratch ----------------
__device__ float g_q[(size_t)BT_*D_];
__device__ float g_k[(size_t)BT_*D_];
__device__ float g_v[(size_t)BT_*D_];
__device__ float g_g[(size_t)BT_*D_];
__device__ float g_gt[B_*H_*T_];
__device__ float g_gc[B_*H_*T_];
__device__ float g_sinbuf [(size_t)B_*H_*NCH_*HD_*HD_];
__device__ float g_sprebuf[(size_t)B_*H_*NCH_*HD_*HD_];
__device__ __nv_bfloat16 g_xhi[(size_t)BT_*D_];
__device__ __nv_bfloat16 g_xlo[(size_t)BT_*D_];
__device__ __nv_bfloat16 g_ohi[(size_t)BT_*D_];
__device__ __nv_bfloat16 g_olo[(size_t)BT_*D_];
__device__ __nv_bfloat16 g_wthi[5*(size_t)D_*D_];   // W^T [N,K]: q,k,v,g,out
__device__ __nv_bfloat16 g_wtlo[5*(size_t)D_*D_];

__device__ __forceinline__ float log_sigmoidf(float z) {
    return (z >= 0.f) ? -log1pf(expf(-z)) : (z - log1pf(expf(z)));
}

// ============================= MMA helpers =============================
__device__ __forceinline__ uint32_t smem_u32(const void* p) {
    uint32_t a;
    asm("{ .reg .u64 t; cvta.to.shared.u64 t, %1; cvt.u32.u64 %0, t; }" : "=r"(a) : "l"(p));
    return a;
}
__device__ __forceinline__ void cp_async16(uint32_t s, const void* g) {
    asm volatile("cp.async.cg.shared.global [%0], [%1], 16;" :: "r"(s), "l"(g));
}
__device__ __forceinline__ void cp_commit() { asm volatile("cp.async.commit_group;"); }
template<int N> __device__ __forceinline__ void cp_wait() {
    asm volatile("cp.async.wait_group %0;" :: "n"(N));
}
__device__ __forceinline__ void ldmat4(uint32_t* r, uint32_t a) {
    asm volatile("ldmatrix.sync.aligned.m8n8.x4.shared.b16 {%0,%1,%2,%3}, [%4];"
        : "=r"(r[0]), "=r"(r[1]), "=r"(r[2]), "=r"(r[3]) : "r"(a));
}
__device__ __forceinline__ void mma_bf16(float* d, const uint32_t* a, uint32_t b0, uint32_t b1) {
    asm volatile(
        "mma.sync.aligned.m16n8k16.row.col.f32.bf16.bf16.f32 "
        "{%0,%1,%2,%3}, {%4,%5,%6,%7}, {%8,%9}, {%0,%1,%2,%3};"
        : "+f"(d[0]), "+f"(d[1]), "+f"(d[2]), "+f"(d[3])
        : "r"(a[0]), "r"(a[1]), "r"(a[2]), "r"(a[3]), "r"(b0), "r"(b1));
}

// ============================= tensor-core GEMM =============================
#define LDS_ROW 72
#define STAGE_A (128 * LDS_ROW * 2)
#define STAGE_T (2 * STAGE_A)
#define NSTG3   3
#define TCG_SMEM (NSTG3 * STAGE_T)

__global__ void __launch_bounds__(128, 2) tc_gemm(
    const __nv_bfloat16* __restrict__ Ahi, const __nv_bfloat16* __restrict__ Alo,
    const __nv_bfloat16* __restrict__ BhiBase, const __nv_bfloat16* __restrict__ BloBase,
    float* __restrict__ C0, float* __restrict__ C1,
    float* __restrict__ C2, float* __restrict__ C3,
    const float* __restrict__ rope_cos, const float* __restrict__ rope_sin)
{
    extern __shared__ __align__(16) char smem[];
    const uint32_t smb = smem_u32(smem);

    int z = blockIdx.z;
    const __nv_bfloat16* Bhi = BhiBase + (size_t)z * D_ * D_;
    const __nv_bfloat16* Blo = BloBase + (size_t)z * D_ * D_;
    float* C = (z == 0) ? C0 : (z == 1) ? C1 : (z == 2) ? C2 : C3;
    bool use_rope = (rope_cos != nullptr) && (z < 2);

    int tid = threadIdx.x, lane = tid & 31, wid = tid >> 5;
    int wm = wid >> 1, wn = wid & 1;
    int m0 = blockIdx.y * 128, n0 = blockIdx.x * 128;

    int row_t = tid >> 3;
    int col_t = (tid & 7) << 3;
    uint32_t so_[8];
#pragma unroll
    for (int i = 0; i < 8; i++)
        so_[i] = (uint32_t)((row_t + 16 * i) * (LDS_ROW * 2) + col_t * 2);

    uint32_t aoff[4];
#pragma unroll
    for (int mt = 0; mt < 4; mt++)
        aoff[mt] = (uint32_t)(((wm * 64 + mt * 16 + (lane & 15)) * LDS_ROW + ((lane >> 4) << 3)) * 2);
    uint32_t boff[4];
    {
        int q = lane >> 3, r = lane & 7;
#pragma unroll
        for (int np = 0; np < 4; np++) {
            int n = wn * 64 + np * 16 + ((q >> 1) << 3) + r;
            int kc = (q & 1) << 3;
            boff[np] = (uint32_t)((n * LDS_ROW + kc) * 2);
        }
    }

    float acc[4][8][4];
#pragma unroll
    for (int i = 0; i < 4; i++)
#pragma unroll
        for (int j = 0; j < 8; j++)
#pragma unroll
            for (int e = 0; e < 4; e++) acc[i][j][e] = 0.f;

    const int NCHUNK = 96;

#pragma unroll
    for (int pc = 0; pc < 2; pc++) {
        int kk = pc << 6;
        uint32_t st = smb + pc * STAGE_T;
#pragma unroll
        for (int i = 0; i < 8; i++) {
            cp_async16(st + so_[i],           Ahi + (size_t)(m0 + row_t + 16 * i) * D_ + kk + col_t);
            cp_async16(st + STAGE_A + so_[i], Bhi + (size_t)(n0 + row_t + 16 * i) * D_ + kk + col_t);
        }
        cp_commit();
    }

    uint32_t fa0[4][4], fb0[4][4], fa1[4][4], fb1[4][4];

#define LDM_BLK(fa, fb, sA, sB, ks) do { \
    _Pragma("unroll") for (int mt = 0; mt < 4; mt++) ldmat4((fa)[mt], (sA) + aoff[mt] + (ks) * 32); \
    _Pragma("unroll") for (int np = 0; np < 4; np++) ldmat4((fb)[np], (sB) + boff[np] + (ks) * 32); \
} while (0)
#define MMA_BLK(fa, fb) do { \
    _Pragma("unroll") for (int mt = 0; mt < 4; mt++) \
        _Pragma("unroll") for (int nt = 0; nt < 8; nt++) \
            mma_bf16(acc[mt][nt], (fa)[mt], (fb)[nt >> 1][(nt & 1) * 2], (fb)[nt >> 1][(nt & 1) * 2 + 1]); \
} while (0)

    int st_c = 0;
    for (int c = 0; c < NCHUNK; c++) {
        cp_wait<1>();
        __syncthreads();

        uint32_t sA = smb + st_c * STAGE_T;
        uint32_t sB = sA + STAGE_A;

        LDM_BLK(fa0, fb0, sA, sB, 0);
        LDM_BLK(fa1, fb1, sA, sB, 1);
        MMA_BLK(fa0, fb0);

        int cn = c + 2;
        if (cn < NCHUNK) {
            int pass = cn >> 5;
            int kk = (cn & 31) << 6;
            const __nv_bfloat16* As = (pass == 1) ? Alo : Ahi;
            const __nv_bfloat16* Bs = (pass == 2) ? Blo : Bhi;
            int stn = st_c + 2; if (stn >= NSTG3) stn -= NSTG3;
            uint32_t st = smb + stn * STAGE_T;
#pragma unroll
            for (int i = 0; i < 8; i++) {
                cp_async16(st + so_[i],           As + (size_t)(m0 + row_t + 16 * i) * D_ + kk + col_t);
                cp_async16(st + STAGE_A + so_[i], Bs + (size_t)(n0 + row_t + 16 * i) * D_ + kk + col_t);
            }
        }
        cp_commit();

        LDM_BLK(fa0, fb0, sA, sB, 2);
        MMA_BLK(fa1, fb1);
        LDM_BLK(fa1, fb1, sA, sB, 3);
        MMA_BLK(fa0, fb0);
        MMA_BLK(fa1, fb1);

        st_c = (st_c + 1 == NSTG3) ? 0 : st_c + 1;
    }

    int tq = lane >> 2, tr = lane & 3;
#pragma unroll
    for (int mt = 0; mt < 4; mt++) {
#pragma unroll
        for (int nt = 0; nt < 8; nt++) {
            int m = m0 + wm * 64 + mt * 16 + tq;
            int n = n0 + wn * 64 + nt * 8 + tr * 2;
            float v0 = acc[mt][nt][0], v1 = acc[mt][nt][1];
            float v2 = acc[mt][nt][2], v3 = acc[mt][nt][3];
            if (use_rope) {
                int i  = (n & 127) >> 1;
                int t1 = m & 4095, t2 = (m + 8) & 4095;
                float c1 = rope_cos[t1 * 64 + i], s1 = rope_sin[t1 * 64 + i];
                float c2 = rope_cos[t2 * 64 + i], s2 = rope_sin[t2 * 64 + i];
                float r0 = v0 * c1 - v1 * s1, r1 = v0 * s1 + v1 * c1;
                float r2 = v2 * c2 - v3 * s2, r3 = v2 * s2 + v3 * c2;
                v0 = r0; v1 = r1; v2 = r2; v3 = r3;
            }
            *(float2*)&C[(size_t)m * D_ + n]       = make_float2(v0, v1);
            *(float2*)&C[(size_t)(m + 8) * D_ + n] = make_float2(v2, v3);
        }
    }
}

// ---------------- fp32 -> bf16 hi/lo split ----------------
__global__ __launch_bounds__(256) void split_kernel(
    const float* __restrict__ a, __nv_bfloat16* __restrict__ hi, __nv_bfloat16* __restrict__ lo)
{
    size_t i = ((size_t)blockIdx.x * 256 + threadIdx.x) * 4;
    float4 v = *(const float4*)&a[i];
    __nv_bfloat16 h0 = __float2bfloat16(v.x), h1 = __float2bfloat16(v.y);
    __nv_bfloat16 h2 = __float2bfloat16(v.z), h3 = __float2bfloat16(v.w);
    __nv_bfloat16 l0 = __float2bfloat16(v.x - __bfloat162float(h0));
    __nv_bfloat16 l1 = __float2bfloat16(v.y - __bfloat162float(h1));
    __nv_bfloat16 l2 = __float2bfloat16(v.z - __bfloat162float(h2));
    __nv_bfloat16 l3 = __float2bfloat16(v.w - __bfloat162float(h3));
    __nv_bfloat162* hp = (__nv_bfloat162*)(hi + i);
    __nv_bfloat162* lp = (__nv_bfloat162*)(lo + i);
    hp[0] = __halves2bfloat162(h0, h1); hp[1] = __halves2bfloat162(h2, h3);
    lp[0] = __halves2bfloat162(l0, l1); lp[1] = __halves2bfloat162(l2, l3);
}

// ---------------- all 5 weights: W[K,N] -> Wt_hi/lo[N,K] transpose+split ----------------
__global__ __launch_bounds__(256) void wsplit_all(
    const float* __restrict__ W0, const float* __restrict__ W1,
    const float* __restrict__ W2, const float* __restrict__ W3,
    const float* __restrict__ W4,
    __nv_bfloat16* __restrict__ hi, __nv_bfloat16* __restrict__ lo)
{
    __shared__ float tile[32][33];
    int z = blockIdx.z;
    const float* W = (z == 0) ? W0 : (z == 1) ? W1 : (z == 2) ? W2 : (z == 3) ? W3 : W4;
    size_t off = (size_t)z * D_ * D_;
    int k0 = blockIdx.y * 32, n0 = blockIdx.x * 32;
    int tx = threadIdx.x & 31, ty = threadIdx.x >> 5;
#pragma unroll
    for (int i = 0; i < 32; i += 8)
        tile[ty + i][tx] = W[(size_t)(k0 + ty + i) * D_ + n0 + tx];
    __syncthreads();
#pragma unroll
    for (int i = 0; i < 32; i += 8) {
        float v = tile[tx][ty + i];
        __nv_bfloat16 h = __float2bfloat16(v);
        __nv_bfloat16 l = __float2bfloat16(v - __bfloat162float(h));
        size_t oi = off + (size_t)(n0 + ty + i) * D_ + k0 + tx;
        hi[oi] = h; lo[oi] = l;
    }
}

// ============================= retention =============================
__global__ __launch_bounds__(128) void gt_kernel(
    const float* __restrict__ x, const float* __restrict__ Wgt, float* __restrict__ gt)
{
    __shared__ float red[64][33];
    int row0 = blockIdx.x * 4;
    int tid = threadIdx.x;
    float acc[4][16];
#pragma unroll
    for (int r = 0; r < 4; r++)
#pragma unroll
        for (int h = 0; h < 16; h++) acc[r][h] = 0.f;

    for (int kk = tid; kk < D_; kk += 128) {
        const float4* w4 = (const float4*)(Wgt + (size_t)kk * 16);
        float4 w0 = w4[0], w1 = w4[1], w2 = w4[2], w3 = w4[3];
        float w[16] = {w0.x, w0.y, w0.z, w0.w, w1.x, w1.y, w1.z, w1.w,
                       w2.x, w2.y, w2.z, w2.w, w3.x, w3.y, w3.z, w3.w};
#pragma unroll
        for (int r = 0; r < 4; r++) {
            float xv = x[(size_t)(row0 + r) * D_ + kk];
#pragma unroll
            for (int h = 0; h < 16; h++) acc[r][h] += xv * w[h];
        }
    }
    int grp = tid >> 2, sub = tid & 3;
#pragma unroll
    for (int half = 0; half < 2; half++) {
        __syncthreads();
#pragma unroll
        for (int r = 0; r < 2; r++) {
            int rr = half * 2 + r;
#pragma unroll
            for (int h = 0; h < 16; h++)
                if (sub == 0) red[(r << 4) + h][grp] = acc[rr][h];
        }
        __syncthreads();
#pragma unroll
        for (int r = 0; r < 2; r++) {
            int rr = half * 2 + r;
#pragma unroll
            for (int h = 0; h < 16; h++)
                if (sub == 1) red[(r << 4) + h][grp] += acc[rr][h];
        }
        __syncthreads();
#pragma unroll
        for (int r = 0; r < 2; r++) {
            int rr = half * 2 + r;
#pragma unroll
            for (int h = 0; h < 16; h++)
                if (sub == 2) red[(r << 4) + h][grp] += acc[rr][h];
        }
        __syncthreads();
#pragma unroll
        for (int r = 0; r < 2; r++) {
            int rr = half * 2 + r;
#pragma unroll
            for (int h = 0; h < 16; h++)
                if (sub == 3) red[(r << 4) + h][grp] += acc[rr][h];
        }
        __syncthreads();
        if (tid < 32) {
            float s = 0.f;
#pragma unroll
            for (int c = 0; c < 32; c++) s += red[tid][c];
            int rr = half * 2 + (tid >> 4);
            int h = tid & 15;
            int row = row0 + rr;
            int b = row >> 12, t = row & 4095;
            gt[((size_t)(b * H_ + h)) * T_ + t] = log_sigmoidf(s) * (1.f / 16.f);
        }
    }
}

__global__ __launch_bounds__(256) void cumsum_kernel(
    const float* __restrict__ gt, float* __restrict__ gc)
{
    int bh = blockIdx.x >> 4;
    int n  = blockIdx.x & 15;
    int tid = threadIdx.x, lane = tid & 31, warp = tid >> 5;
    size_t idx = (size_t)bh * T_ + n * CH_ + tid;
    float v = gt[idx];
#pragma unroll
    for (int off = 1; off < 32; off <<= 1) {
        float y = __shfl_up_sync(0xffffffffu, v, off);
        if (lane >= off) v += y;
    }
    __shared__ float ws[8];
    if (lane == 31) ws[warp] = v;
    __syncthreads();
    if (tid == 0) {
        float s = 0.f;
#pragma unroll
        for (int w = 0; w < 8; w++) { float t = ws[w]; ws[w] = s; s += t; }
    }
    __syncthreads();
    gc[idx] = v + ws[warp];
}

// ---------------- tensor-core S_in: S_in[d][e] = sum_s (K[s][d]*kd[s]) * V[s][e] ----------------
#define SIN_KS_F   0
#define SIN_VS_F   (32*132)
#define SIN_KTH_B  (2*32*132*4)
#define SIN_KTL_B  (SIN_KTH_B + 128*40*2)
#define SIN_VTH_B  (SIN_KTL_B + 128*40*2)
#define SIN_VTL_B  (SIN_VTH_B + 128*40*2)
#define SIN_SMEM   (SIN_VTL_B + 128*40*2)

__global__ __launch_bounds__(256) void sin_tc_kernel(
    const float* __restrict__ k, const float* __restrict__ v,
    const float* __restrict__ gc, float* __restrict__ Sin)
{
    extern __shared__ __align__(16) char smc[];
    float* Ks = (float*)smc;
    float* Vs = (float*)smc + SIN_VS_F;
    __nv_bfloat162* KTh = (__nv_bfloat162*)(smc + SIN_KTH_B);
    __nv_bfloat162* KTl = (__nv_bfloat162*)(smc + SIN_KTL_B);
    __nv_bfloat162* VTh = (__nv_bfloat162*)(smc + SIN_VTH_B);
    __nv_bfloat162* VTl = (__nv_bfloat162*)(smc + SIN_VTL_B);
    __shared__ float kd[32];
    const uint32_t smb = smem_u32(smc);

    int blk = blockIdx.x;
    int n = blk & 15, h = (blk >> 4) & 15, b = blk >> 8;
    int tid = threadIdx.x, lane = tid & 31, wid = tid >> 5;
    int wm = wid >> 2, wn = wid & 3;
    const float* gcc = gc + ((size_t)(b * H_ + h)) * T_ + n * CH_;
    float gtot = gcc[CH_ - 1];
    int rowbase = b * T_ + n * CH_;

    uint32_t aoff[4];
#pragma unroll
    for (int mt = 0; mt < 4; mt++)
        aoff[mt] = (uint32_t)((wm * 64 + mt * 16 + (lane & 15)) * 80 + ((lane >> 4) << 4));
    uint32_t boff[2];
    {
        int q = lane >> 3, r = lane & 7;
#pragma unroll
        for (int np = 0; np < 2; np++) {
            int nr = wn * 32 + np * 16 + ((q >> 1) << 3) + r;
            boff[np] = (uint32_t)(nr * 80 + ((q & 1) << 4));
        }
    }

    float acc[4][4][4];
#pragma unroll
    for (int i = 0; i < 4; i++)
#pragma unroll
        for (int j = 0; j < 4; j++)
#pragma unroll
            for (int e = 0; e < 4; e++) acc[i][j][e] = 0.f;

    int d = tid & 127, sh = tid >> 7;

    for (int slab = 0; slab < 8; slab++) {
        int s_base = slab * 32;
        if (tid < 32) kd[tid] = expf(gtot - gcc[s_base + tid]) * SCALE_;
#pragma unroll
        for (int l = 0; l < 4; l++) {
            int li = tid + l * 256;
            int c = li >> 5, gcol = (li & 31) << 2;
            size_t gi = ((size_t)(rowbase + s_base + c)) * D_ + h * HD_ + gcol;
            *(float4*)&Ks[c * 132 + gcol] = *(const float4*)&k[gi];
            *(float4*)&Vs[c * 132 + gcol] = *(const float4*)&v[gi];
        }
        __syncthreads();

#pragma unroll
        for (int j = 0; j < 8; j++) {
            int s0 = sh * 16 + 2 * j;
            float ka = Ks[s0 * 132 + d] * kd[s0];
            float kb = Ks[(s0 + 1) * 132 + d] * kd[s0 + 1];
            float va = Vs[s0 * 132 + d];
            float vb = Vs[(s0 + 1) * 132 + d];
            __nv_bfloat16 kah = __float2bfloat16(ka), kbh = __float2bfloat16(kb);
            __nv_bfloat16 vah = __float2bfloat16(va), vbh = __float2bfloat16(vb);
            int oi = d * 20 + sh * 8 + j;
            KTh[oi] = __halves2bfloat162(kah, kbh);
            KTl[oi] = __halves2bfloat162(__float2bfloat16(ka - __bfloat162float(kah)),
                                         __float2bfloat16(kb - __bfloat162float(kbh)));
            VTh[oi] = __halves2bfloat162(vah, vbh);
            VTl[oi] = __halves2bfloat162(__float2bfloat16(va - __bfloat162float(vah)),
                                         __float2bfloat16(vb - __bfloat162float(vbh)));
        }
        __syncthreads();

#pragma unroll
        for (int pass = 0; pass < 3; pass++) {
            uint32_t Ab = smb + ((pass == 1) ? SIN_KTL_B : SIN_KTH_B);
            uint32_t Bb = smb + ((pass == 2) ? SIN_VTL_B : SIN_VTH_B);
#pragma unroll
            for (int ks = 0; ks < 2; ks++) {
                uint32_t fa[4][4], fb[2][4];
#pragma unroll
                for (int mt = 0; mt < 4; mt++) ldmat4(fa[mt], Ab + aoff[mt] + ks * 32);
#pragma unroll
                for (int np = 0; np < 2; np++) ldmat4(fb[np], Bb + boff[np] + ks * 32);
#pragma unroll
                for (int mt = 0; mt < 4; mt++)
#pragma unroll
                    for (int nt = 0; nt < 4; nt++)
                        mma_bf16(acc[mt][nt], fa[mt],
                                 fb[nt >> 1][(nt & 1) * 2], fb[nt >> 1][(nt & 1) * 2 + 1]);
            }
        }
        __syncthreads();
    }

    size_t base = (size_t)blk * (HD_ * HD_);
    int tq = lane >> 2, tr = lane & 3;
#pragma unroll
    for (int mt = 0; mt < 4; mt++) {
#pragma unroll
        for (int nt = 0; nt < 4; nt++) {
            int m = wm * 64 + mt * 16 + tq;
            int nn = wn * 32 + nt * 8 + tr * 2;
            *(float2*)&Sin[base + (size_t)m * HD_ + nn]       = make_float2(acc[mt][nt][0], acc[mt][nt][1]);
            *(float2*)&Sin[base + (size_t)(m + 8) * HD_ + nn] = make_float2(acc[mt][nt][2], acc[mt][nt][3]);
        }
    }
}

// parallel over (bh, 8 parts); serial only over 16 chunks
__global__ __launch_bounds__(256) void scan_kernel(
    const float* __restrict__ Sin, const float* __restrict__ gc, float* __restrict__ Spre)
{
    int blk = blockIdx.x;
    int bh = blk >> 3, part = blk & 7;
    int e0 = part * 2048 + threadIdx.x;
    float S[8];
#pragma unroll
    for (int l = 0; l < 8; l++) S[l] = 0.f;
    for (int n = 0; n < NCH_; n++) {
        float cd = expf(gc[(size_t)bh * T_ + n * CH_ + (CH_ - 1)]);
        size_t base = ((size_t)(bh * NCH_ + n)) * (HD_ * HD_);
#pragma unroll
        for (int l = 0; l < 8; l++) {
            int idx = e0 + l * 256;
            Spre[base + idx] = S[l];
            S[l] = S[l] * cd + Sin[base + idx];
        }
    }
}

#define QS_OFF  0
#define BS_OFF  8192
#define SS_OFF  16384
#define GQ_OFF  20736
#define GK_OFF  20800
#define RED_OFF 20864
#define SMF_TOT 21888

__global__ __launch_bounds__(256) void out_kernel(
    const float* __restrict__ q, const float* __restrict__ k,
    const float* __restrict__ v, const float* __restrict__ g,
    const float* __restrict__ gc, const float* __restrict__ Spre,
    __nv_bfloat16* __restrict__ ohi, __nv_bfloat16* __restrict__ olo)
{
    extern __shared__ __align__(16) float sm[];
    float* Qs  = sm + QS_OFF;
    float* Bs  = sm + BS_OFF;
    float* Ss  = sm + SS_OFF;
    float* gq  = sm + GQ_OFF;
    float* gk  = sm + GK_OFF;
    float* red = sm + RED_OFF;

    int blk = blockIdx.x;
    int rt = blk & 3, n = (blk >> 2) & 15, h = (blk >> 6) & 15, b = blk >> 10;
    int tid = threadIdx.x, trow = tid >> 4, tcol = tid & 15;
    int trow4 = trow * 4;
    const float* gcc = gc + ((size_t)(b * H_ + h)) * T_ + n * CH_;
    int c0 = rt * 64;
    int rowbase = b * T_ + n * CH_;

#pragma unroll
    for (int l = 0; l < 8; l++) {
        int li = tid + l * 256;
        int c = li >> 5, gcol = (li & 31) << 2;
        size_t gi = ((size_t)(rowbase + c0 + c)) * D_ + h * HD_ + gcol;
        *(float4*)&Qs[c * 128 + gcol] = *(const float4*)&q[gi];
    }
    if (tid < 64) gq[tid] = gcc[c0 + tid];

    float oacc[4][8];
#pragma unroll
    for (int i = 0; i < 4; i++)
#pragma unroll
        for (int j = 0; j < 8; j++) oacc[i][j] = 0.f;
    __syncthreads();

    for (int st = 0; st <= rt; st++) {
        int s0 = st * 64;
#pragma unroll
        for (int l = 0; l < 8; l++) {
            int li = tid + l * 256;
            int c = li >> 5, gr = li & 31;
            size_t gi = ((size_t)(rowbase + s0 + c)) * D_ + h * HD_ + (gr << 2);
            *(float4*)&Bs[c * 128 + ((gr ^ (c & 7)) << 2)] = *(const float4*)&k[gi];
        }
        if (tid < 64) gk[tid] = gcc[s0 + tid];
        __syncthreads();

        float sacc[4][4];
#pragma unroll
        for (int i = 0; i < 4; i++)
#pragma unroll
            for (int j = 0; j < 4; j++) sacc[i][j] = 0.f;
#pragma unroll
        for (int gr = 0; gr < 32; gr++) {
            float4 a[4];
#pragma unroll
            for (int i = 0; i < 4; i++) a[i] = *(float4*)&Qs[(trow4 + i) * 128 + (gr << 2)];
#pragma unroll
            for (int j = 0; j < 4; j++) {
                int s = tcol * 4 + j;
                float4 bb = *(float4*)&Bs[s * 128 + ((gr ^ (s & 7)) << 2)];
#pragma unroll
                for (int i = 0; i < 4; i++)
                    sacc[i][j] += a[i].x * bb.x + a[i].y * bb.y + a[i].z * bb.z + a[i].w * bb.w;
            }
        }
#pragma unroll
        for (int i = 0; i < 4; i++) {
            int r = trow4 + i;
            float gqi = gq[r];
#pragma unroll
            for (int j = 0; j < 4; j++) {
                int s = tcol * 4 + j;
                float val = 0.f;
                if (s0 + s <= c0 + r) val = sacc[i][j] * SCALE_ * expf(gqi - gk[s]);
                Ss[r * 68 + s] = val;
            }
        }
        __syncthreads();

#pragma unroll
        for (int l = 0; l < 8; l++) {
            int li = tid + l * 256;
            int c = li >> 5, gr = li & 31;
            size_t gi = ((size_t)(rowbase + s0 + c)) * D_ + h * HD_ + (gr << 2);
            *(float4*)&Bs[c * 128 + ((gr ^ (c & 7)) << 2)] = *(const float4*)&v[gi];
        }
        __syncthreads();

#pragma unroll
        for (int s = 0; s < 64; s++) {
            float4 b0 = *(float4*)&Bs[s * 128 + (((2 * tcol)     ^ (s & 7)) << 2)];
            float4 b1 = *(float4*)&Bs[s * 128 + (((2 * tcol + 1) ^ (s & 7)) << 2)];
#pragma unroll
            for (int i = 0; i < 4; i++) {
                float a = Ss[(trow4 + i) * 68 + s];
                oacc[i][0] += a * b0.x; oacc[i][1] += a * b0.y;
                oacc[i][2] += a * b0.z; oacc[i][3] += a * b0.w;
                oacc[i][4] += a * b1.x; oacc[i][5] += a * b1.y;
                oacc[i][6] += a * b1.z; oacc[i][7] += a * b1.w;
            }
        }
        __syncthreads();
    }

    float qd[4];
#pragma unroll
    for (int i = 0; i < 4; i++) qd[i] = expf(gq[trow4 + i]);
    size_t sbase = ((size_t)(blk >> 2)) * (HD_ * HD_);
    for (int d0 = 0; d0 < 128; d0 += 64) {
#pragma unroll
        for (int l = 0; l < 8; l++) {
            int li = tid + l * 256;
            int dd = li >> 5, gr = li & 31;
            *(float4*)&Bs[dd * 128 + ((gr ^ (dd & 7)) << 2)] =
                *(const float4*)&Spre[sbase + (size_t)(d0 + dd) * 128 + (gr << 2)];
        }
        __syncthreads();
#pragma unroll
        for (int dd = 0; dd < 64; dd++) {
            float4 b0 = *(float4*)&Bs[dd * 128 + (((2 * tcol)     ^ (dd & 7)) << 2)];
            float4 b1 = *(float4*)&Bs[dd * 128 + (((2 * tcol + 1) ^ (dd & 7)) << 2)];
#pragma unroll
            for (int i = 0; i < 4; i++) {
                float a = Qs[(trow4 + i) * 128 + d0 + dd] * qd[i];
                oacc[i][0] += a * b0.x; oacc[i][1] += a * b0.y;
                oacc[i][2] += a * b0.z; oacc[i][3] += a * b0.w;
                oacc[i][4] += a * b1.x; oacc[i][5] += a * b1.y;
                oacc[i][6] += a * b1.z; oacc[i][7] += a * b1.w;
            }
        }
        __syncthreads();
    }

#pragma unroll
    for (int i = 0; i < 4; i++) {
        float ss = 0.f;
#pragma unroll
        for (int j = 0; j < 8; j++) ss += oacc[i][j] * oacc[i][j];
        red[(trow4 + i) * 16 + tcol] = ss;
    }
    __syncthreads();
#pragma unroll
    for (int i = 0; i < 4; i++) {
        int r = trow4 + i;
        float ss = 0.f;
#pragma unroll
        for (int t2 = 0; t2 < 16; t2++) ss += red[r * 16 + t2];
        float rn = rsqrtf(ss * (1.0f / 128.0f) + 1e-5f);
        size_t gi = ((size_t)(rowbase + c0 + r)) * D_ + h * HD_ + tcol * 8;
        float4 g0 = *(const float4*)&g[gi];
        float4 g1 = *(const float4*)&g[gi + 4];
        float ov[8];
        ov[0] = oacc[i][0] * rn * (g0.x / (1.f + expf(-g0.x)));
        ov[1] = oacc[i][1] * rn * (g0.y / (1.f + expf(-g0.y)));
        ov[2] = oacc[i][2] * rn * (g0.z / (1.f + expf(-g0.z)));
        ov[3] = oacc[i][3] * rn * (g0.w / (1.f + expf(-g0.w)));
        ov[4] = oacc[i][4] * rn * (g1.x / (1.f + expf(-g1.x)));
        ov[5] = oacc[i][5] * rn * (g1.y / (1.f + expf(-g1.y)));
        ov[6] = oacc[i][6] * rn * (g1.z / (1.f + expf(-g1.z)));
        ov[7] = oacc[i][7] * rn * (g1.w / (1.f + expf(-g1.w)));
        __nv_bfloat162 hv[4], lv[4];
#pragma unroll
        for (int j = 0; j < 4; j++) {
            __nv_bfloat16 h0 = __float2bfloat16(ov[2*j]);
            __nv_bfloat16 h1 = __float2bfloat16(ov[2*j+1]);
            __nv_bfloat16 l0 = __float2bfloat16(ov[2*j]   - __bfloat162float(h0));
            __nv_bfloat16 l1 = __float2bfloat16(ov[2*j+1] - __bfloat162float(h1));
            hv[j] = __halves2bfloat162(h0, h1);
            lv[j] = __halves2bfloat162(l0, l1);
        }
        *(uint4*)&ohi[gi] = *(uint4*)hv;
        *(uint4*)&olo[gi] = *(uint4*)lv;
    }
}

// ============================= launcher =============================
extern "C" void kernel_launch(void* const* d_in, const int* in_sizes, int n_in,
                              void* d_out, int out_size)
{
    const float* x    = (const float*)d_in[0];
    const float* cosb = (const float*)d_in[1];
    const float* sinb = (const float*)d_in[2];
    const float* Wq   = (const float*)d_in[3];
    const float* Wk   = (const float*)d_in[4];
    const float* Wv   = (const float*)d_in[5];
    const float* Wg   = (const float*)d_in[6];
    const float* Wgt  = (const float*)d_in[7];
    const float* Wout = (const float*)d_in[8];
    float* out = (float*)d_out;

    float *q, *k, *v, *g, *gt, *gc, *sbuf, *spre;
    __nv_bfloat16 *xhi, *xlo, *ohi, *olo, *wthi, *wtlo;
    cudaGetSymbolAddress((void**)&q,    g_q);
    cudaGetSymbolAddress((void**)&k,    g_k);
    cudaGetSymbolAddress((void**)&v,    g_v);
    cudaGetSymbolAddress((void**)&g,    g_g);
    cudaGetSymbolAddress((void**)&gt,   g_gt);
    cudaGetSymbolAddress((void**)&gc,   g_gc);
    cudaGetSymbolAddress((void**)&sbuf, g_sinbuf);
    cudaGetSymbolAddress((void**)&spre, g_sprebuf);
    cudaGetSymbolAddress((void**)&xhi,  g_xhi);
    cudaGetSymbolAddress((void**)&xlo,  g_xlo);
    cudaGetSymbolAddress((void**)&ohi,  g_ohi);
    cudaGetSymbolAddress((void**)&olo,  g_olo);
    cudaGetSymbolAddress((void**)&wthi, g_wthi);
    cudaGetSymbolAddress((void**)&wtlo, g_wtlo);

    cudaFuncSetAttribute(out_kernel, cudaFuncAttributeMaxDynamicSharedMemorySize,
                         SMF_TOT * sizeof(float));
    cudaFuncSetAttribute(tc_gemm, cudaFuncAttributeMaxDynamicSharedMemorySize, TCG_SMEM);
    cudaFuncSetAttribute(sin_tc_kernel, cudaFuncAttributeMaxDynamicSharedMemorySize, SIN_SMEM);

    const size_t WSZ = (size_t)D_ * D_;
    dim3 wgrid(D_ / 32, D_ / 32, 5);
    dim3 ggrid4(D_ / 128, BT_ / 128, 4);
    dim3 ggrid1(D_ / 128, BT_ / 128, 1);

    wsplit_all<<<wgrid, 256>>>(Wq, Wk, Wv, Wg, Wout, wthi, wtlo);        // 1
    split_kernel<<<(BT_ * (D_ / 4)) / 256, 256>>>(x, xhi, xlo);          // 2
    gt_kernel<<<BT_ / 4, 128>>>(x, Wgt, gt);                             // 3
    cumsum_kernel<<<B_ * H_ * NCH_, 256>>>(gt, gc);                      // 4
    tc_gemm<<<ggrid4, 128, TCG_SMEM>>>(xhi, xlo, wthi, wtlo, q, k, v, g, cosb, sinb); // 5
    sin_tc_kernel<<<B_ * H_ * NCH_, 256, SIN_SMEM>>>(k, v, gc, sbuf);    // 6 <- ncu
    scan_kernel<<<B_ * H_ * 8, 256>>>(sbuf, gc, spre);
    out_kernel<<<B_ * H_ * NCH_ * 4, 256, SMF_TOT * sizeof(float)>>>(q, k, v, g, gc, spre, ohi, olo);
    tc_gemm<<<ggrid1, 128, TCG_SMEM>>>(ohi, olo, wthi + 4 * WSZ, wtlo + 4 * WSZ,
                                       out, out, out, out, nullptr, nullptr);
}

// round 17
// speedup vs baseline: 1.1564x; 1.1564x over previous
#include <cuda_runtime.h>
#include <cuda_bf16.h>
#include <cstdint>

#define B_   2
#define T_   4096
#define D_   2048
#define H_   16
#define HD_  128
#define CH_  256
#define NCH_ 16
#define BT_  (B_*T_)
#define SCALE_ 0.08838834764831845f

// ---------------- scratch ----------------
__device__ float g_q[(size_t)BT_*D_];
__device__ float g_k[(size_t)BT_*D_];
__device__ float g_v[(size_t)BT_*D_];
__device__ float g_g[(size_t)BT_*D_];
__device__ float g_gt[B_*H_*T_];
__device__ float g_gc[B_*H_*T_];
__device__ float g_sinbuf [(size_t)B_*H_*NCH_*HD_*HD_];
__device__ float g_sprebuf[(size_t)B_*H_*NCH_*HD_*HD_];
__device__ __nv_bfloat16 g_xhi[(size_t)BT_*D_];
__device__ __nv_bfloat16 g_xlo[(size_t)BT_*D_];
__device__ __nv_bfloat16 g_ohi[(size_t)BT_*D_];
__device__ __nv_bfloat16 g_olo[(size_t)BT_*D_];
__device__ __nv_bfloat16 g_wthi[5*(size_t)D_*D_];   // W^T [N,K]: q,k,v,g,out
__device__ __nv_bfloat16 g_wtlo[5*(size_t)D_*D_];

__device__ __forceinline__ float log_sigmoidf(float z) {
    return (z >= 0.f) ? -log1pf(expf(-z)) : (z - log1pf(expf(z)));
}

// ============================= MMA helpers =============================
__device__ __forceinline__ uint32_t smem_u32(const void* p) {
    uint32_t a;
    asm("{ .reg .u64 t; cvta.to.shared.u64 t, %1; cvt.u32.u64 %0, t; }" : "=r"(a) : "l"(p));
    return a;
}
__device__ __forceinline__ void cp_async16(uint32_t s, const void* g) {
    asm volatile("cp.async.cg.shared.global [%0], [%1], 16;" :: "r"(s), "l"(g));
}
__device__ __forceinline__ void cp_commit() { asm volatile("cp.async.commit_group;"); }
template<int N> __device__ __forceinline__ void cp_wait() {
    asm volatile("cp.async.wait_group %0;" :: "n"(N));
}
__device__ __forceinline__ void ldmat4(uint32_t* r, uint32_t a) {
    asm volatile("ldmatrix.sync.aligned.m8n8.x4.shared.b16 {%0,%1,%2,%3}, [%4];"
        : "=r"(r[0]), "=r"(r[1]), "=r"(r[2]), "=r"(r[3]) : "r"(a));
}
__device__ __forceinline__ void mma_bf16(float* d, const uint32_t* a, uint32_t b0, uint32_t b1) {
    asm volatile(
        "mma.sync.aligned.m16n8k16.row.col.f32.bf16.bf16.f32 "
        "{%0,%1,%2,%3}, {%4,%5,%6,%7}, {%8,%9}, {%0,%1,%2,%3};"
        : "+f"(d[0]), "+f"(d[1]), "+f"(d[2]), "+f"(d[3])
        : "r"(a[0]), "r"(a[1]), "r"(a[2]), "r"(a[3]), "r"(b0), "r"(b1));
}
__device__ __forceinline__ __nv_bfloat162 hi2_of(float a, float b) {
    return __halves2bfloat162(__float2bfloat16(a), __float2bfloat16(b));
}
__device__ __forceinline__ __nv_bfloat162 lo2_of(float a, float b) {
    __nv_bfloat16 ah = __float2bfloat16(a), bh = __float2bfloat16(b);
    return __halves2bfloat162(__float2bfloat16(a - __bfloat162float(ah)),
                              __float2bfloat16(b - __bfloat162float(bh)));
}

// ============================= tensor-core GEMM =============================
#define LDS_ROW 72
#define STAGE_A (128 * LDS_ROW * 2)
#define STAGE_T (2 * STAGE_A)
#define NSTG3   3
#define TCG_SMEM (NSTG3 * STAGE_T)

__global__ void __launch_bounds__(128, 2) tc_gemm(
    const __nv_bfloat16* __restrict__ Ahi, const __nv_bfloat16* __restrict__ Alo,
    const __nv_bfloat16* __restrict__ BhiBase, const __nv_bfloat16* __restrict__ BloBase,
    float* __restrict__ C0, float* __restrict__ C1,
    float* __restrict__ C2, float* __restrict__ C3,
    const float* __restrict__ rope_cos, const float* __restrict__ rope_sin)
{
    extern __shared__ __align__(16) char smem[];
    const uint32_t smb = smem_u32(smem);

    int z = blockIdx.z;
    const __nv_bfloat16* Bhi = BhiBase + (size_t)z * D_ * D_;
    const __nv_bfloat16* Blo = BloBase + (size_t)z * D_ * D_;
    float* C = (z == 0) ? C0 : (z == 1) ? C1 : (z == 2) ? C2 : C3;
    bool use_rope = (rope_cos != nullptr) && (z < 2);

    int tid = threadIdx.x, lane = tid & 31, wid = tid >> 5;
    int wm = wid >> 1, wn = wid & 1;
    int m0 = blockIdx.y * 128, n0 = blockIdx.x * 128;

    int row_t = tid >> 3;
    int col_t = (tid & 7) << 3;
    uint32_t so_[8];
#pragma unroll
    for (int i = 0; i < 8; i++)
        so_[i] = (uint32_t)((row_t + 16 * i) * (LDS_ROW * 2) + col_t * 2);

    uint32_t aoff[4];
#pragma unroll
    for (int mt = 0; mt < 4; mt++)
        aoff[mt] = (uint32_t)(((wm * 64 + mt * 16 + (lane & 15)) * LDS_ROW + ((lane >> 4) << 3)) * 2);
    uint32_t boff[4];
    {
        int q = lane >> 3, r = lane & 7;
#pragma unroll
        for (int np = 0; np < 4; np++) {
            int n = wn * 64 + np * 16 + ((q >> 1) << 3) + r;
            int kc = (q & 1) << 3;
            boff[np] = (uint32_t)((n * LDS_ROW + kc) * 2);
        }
    }

    float acc[4][8][4];
#pragma unroll
    for (int i = 0; i < 4; i++)
#pragma unroll
        for (int j = 0; j < 8; j++)
#pragma unroll
            for (int e = 0; e < 4; e++) acc[i][j][e] = 0.f;

    const int NCHUNK = 96;

#pragma unroll
    for (int pc = 0; pc < 2; pc++) {
        int kk = pc << 6;
        uint32_t st = smb + pc * STAGE_T;
#pragma unroll
        for (int i = 0; i < 8; i++) {
            cp_async16(st + so_[i],           Ahi + (size_t)(m0 + row_t + 16 * i) * D_ + kk + col_t);
            cp_async16(st + STAGE_A + so_[i], Bhi + (size_t)(n0 + row_t + 16 * i) * D_ + kk + col_t);
        }
        cp_commit();
    }

    uint32_t fa0[4][4], fb0[4][4], fa1[4][4], fb1[4][4];

#define LDM_BLK(fa, fb, sA, sB, ks) do { \
    _Pragma("unroll") for (int mt = 0; mt < 4; mt++) ldmat4((fa)[mt], (sA) + aoff[mt] + (ks) * 32); \
    _Pragma("unroll") for (int np = 0; np < 4; np++) ldmat4((fb)[np], (sB) + boff[np] + (ks) * 32); \
} while (0)
#define MMA_BLK(fa, fb) do { \
    _Pragma("unroll") for (int mt = 0; mt < 4; mt++) \
        _Pragma("unroll") for (int nt = 0; nt < 8; nt++) \
            mma_bf16(acc[mt][nt], (fa)[mt], (fb)[nt >> 1][(nt & 1) * 2], (fb)[nt >> 1][(nt & 1) * 2 + 1]); \
} while (0)

    int st_c = 0;
    for (int c = 0; c < NCHUNK; c++) {
        cp_wait<1>();
        __syncthreads();

        uint32_t sA = smb + st_c * STAGE_T;
        uint32_t sB = sA + STAGE_A;

        LDM_BLK(fa0, fb0, sA, sB, 0);
        LDM_BLK(fa1, fb1, sA, sB, 1);
        MMA_BLK(fa0, fb0);

        int cn = c + 2;
        if (cn < NCHUNK) {
            int pass = cn >> 5;
            int kk = (cn & 31) << 6;
            const __nv_bfloat16* As = (pass == 1) ? Alo : Ahi;
            const __nv_bfloat16* Bs = (pass == 2) ? Blo : Bhi;
            int stn = st_c + 2; if (stn >= NSTG3) stn -= NSTG3;
            uint32_t st = smb + stn * STAGE_T;
#pragma unroll
            for (int i = 0; i < 8; i++) {
                cp_async16(st + so_[i],           As + (size_t)(m0 + row_t + 16 * i) * D_ + kk + col_t);
                cp_async16(st + STAGE_A + so_[i], Bs + (size_t)(n0 + row_t + 16 * i) * D_ + kk + col_t);
            }
        }
        cp_commit();

        LDM_BLK(fa0, fb0, sA, sB, 2);
        MMA_BLK(fa1, fb1);
        LDM_BLK(fa1, fb1, sA, sB, 3);
        MMA_BLK(fa0, fb0);
        MMA_BLK(fa1, fb1);

        st_c = (st_c + 1 == NSTG3) ? 0 : st_c + 1;
    }

    int tq = lane >> 2, tr = lane & 3;
#pragma unroll
    for (int mt = 0; mt < 4; mt++) {
#pragma unroll
        for (int nt = 0; nt < 8; nt++) {
            int m = m0 + wm * 64 + mt * 16 + tq;
            int n = n0 + wn * 64 + nt * 8 + tr * 2;
            float v0 = acc[mt][nt][0], v1 = acc[mt][nt][1];
            float v2 = acc[mt][nt][2], v3 = acc[mt][nt][3];
            if (use_rope) {
                int i  = (n & 127) >> 1;
                int t1 = m & 4095, t2 = (m + 8) & 4095;
                float c1 = rope_cos[t1 * 64 + i], s1 = rope_sin[t1 * 64 + i];
                float c2 = rope_cos[t2 * 64 + i], s2 = rope_sin[t2 * 64 + i];
                float r0 = v0 * c1 - v1 * s1, r1 = v0 * s1 + v1 * c1;
                float r2 = v2 * c2 - v3 * s2, r3 = v2 * s2 + v3 * c2;
                v0 = r0; v1 = r1; v2 = r2; v3 = r3;
            }
            *(float2*)&C[(size_t)m * D_ + n]       = make_float2(v0, v1);
            *(float2*)&C[(size_t)(m + 8) * D_ + n] = make_float2(v2, v3);
        }
    }
}

// ---------------- fp32 -> bf16 hi/lo split ----------------
__global__ __launch_bounds__(256) void split_kernel(
    const float* __restrict__ a, __nv_bfloat16* __restrict__ hi, __nv_bfloat16* __restrict__ lo)
{
    size_t i = ((size_t)blockIdx.x * 256 + threadIdx.x) * 4;
    float4 v = *(const float4*)&a[i];
    __nv_bfloat162* hp = (__nv_bfloat162*)(hi + i);
    __nv_bfloat162* lp = (__nv_bfloat162*)(lo + i);
    hp[0] = hi2_of(v.x, v.y); hp[1] = hi2_of(v.z, v.w);
    lp[0] = lo2_of(v.x, v.y); lp[1] = lo2_of(v.z, v.w);
}

// ---------------- all 5 weights: W[K,N] -> Wt_hi/lo[N,K] transpose+split ----------------
__global__ __launch_bounds__(256) void wsplit_all(
    const float* __restrict__ W0, const float* __restrict__ W1,
    const float* __restrict__ W2, const float* __restrict__ W3,
    const float* __restrict__ W4,
    __nv_bfloat16* __restrict__ hi, __nv_bfloat16* __restrict__ lo)
{
    __shared__ float tile[32][33];
    int z = blockIdx.z;
    const float* W = (z == 0) ? W0 : (z == 1) ? W1 : (z == 2) ? W2 : (z == 3) ? W3 : W4;
    size_t off = (size_t)z * D_ * D_;
    int k0 = blockIdx.y * 32, n0 = blockIdx.x * 32;
    int tx = threadIdx.x & 31, ty = threadIdx.x >> 5;
#pragma unroll
    for (int i = 0; i < 32; i += 8)
        tile[ty + i][tx] = W[(size_t)(k0 + ty + i) * D_ + n0 + tx];
    __syncthreads();
#pragma unroll
    for (int i = 0; i < 32; i += 8) {
        float v = tile[tx][ty + i];
        __nv_bfloat16 h = __float2bfloat16(v);
        __nv_bfloat16 l = __float2bfloat16(v - __bfloat162float(h));
        size_t oi = off + (size_t)(n0 + ty + i) * D_ + k0 + tx;
        hi[oi] = h; lo[oi] = l;
    }
}

// ============================= retention =============================
__global__ __launch_bounds__(128) void gt_kernel(
    const float* __restrict__ x, const float* __restrict__ Wgt, float* __restrict__ gt)
{
    __shared__ float red[64][33];
    int row0 = blockIdx.x * 4;
    int tid = threadIdx.x;
    float acc[4][16];
#pragma unroll
    for (int r = 0; r < 4; r++)
#pragma unroll
        for (int h = 0; h < 16; h++) acc[r][h] = 0.f;

    for (int kk = tid; kk < D_; kk += 128) {
        const float4* w4 = (const float4*)(Wgt + (size_t)kk * 16);
        float4 w0 = w4[0], w1 = w4[1], w2 = w4[2], w3 = w4[3];
        float w[16] = {w0.x, w0.y, w0.z, w0.w, w1.x, w1.y, w1.z, w1.w,
                       w2.x, w2.y, w2.z, w2.w, w3.x, w3.y, w3.z, w3.w};
#pragma unroll
        for (int r = 0; r < 4; r++) {
            float xv = x[(size_t)(row0 + r) * D_ + kk];
#pragma unroll
            for (int h = 0; h < 16; h++) acc[r][h] += xv * w[h];
        }
    }
    int grp = tid >> 2, sub = tid & 3;
#pragma unroll
    for (int half = 0; half < 2; half++) {
        __syncthreads();
#pragma unroll
        for (int r = 0; r < 2; r++) {
            int rr = half * 2 + r;
#pragma unroll
            for (int h = 0; h < 16; h++)
                if (sub == 0) red[(r << 4) + h][grp] = acc[rr][h];
        }
        __syncthreads();
#pragma unroll
        for (int r = 0; r < 2; r++) {
            int rr = half * 2 + r;
#pragma unroll
            for (int h = 0; h < 16; h++)
                if (sub == 1) red[(r << 4) + h][grp] += acc[rr][h];
        }
        __syncthreads();
#pragma unroll
        for (int r = 0; r < 2; r++) {
            int rr = half * 2 + r;
#pragma unroll
            for (int h = 0; h < 16; h++)
                if (sub == 2) red[(r << 4) + h][grp] += acc[rr][h];
        }
        __syncthreads();
#pragma unroll
        for (int r = 0; r < 2; r++) {
            int rr = half * 2 + r;
#pragma unroll
            for (int h = 0; h < 16; h++)
                if (sub == 3) red[(r << 4) + h][grp] += acc[rr][h];
        }
        __syncthreads();
        if (tid < 32) {
            float s = 0.f;
#pragma unroll
            for (int c = 0; c < 32; c++) s += red[tid][c];
            int rr = half * 2 + (tid >> 4);
            int h = tid & 15;
            int row = row0 + rr;
            int b = row >> 12, t = row & 4095;
            gt[((size_t)(b * H_ + h)) * T_ + t] = log_sigmoidf(s) * (1.f / 16.f);
        }
    }
}

__global__ __launch_bounds__(256) void cumsum_kernel(
    const float* __restrict__ gt, float* __restrict__ gc)
{
    int bh = blockIdx.x >> 4;
    int n  = blockIdx.x & 15;
    int tid = threadIdx.x, lane = tid & 31, warp = tid >> 5;
    size_t idx = (size_t)bh * T_ + n * CH_ + tid;
    float v = gt[idx];
#pragma unroll
    for (int off = 1; off < 32; off <<= 1) {
        float y = __shfl_up_sync(0xffffffffu, v, off);
        if (lane >= off) v += y;
    }
    __shared__ float ws[8];
    if (lane == 31) ws[warp] = v;
    __syncthreads();
    if (tid == 0) {
        float s = 0.f;
#pragma unroll
        for (int w = 0; w < 8; w++) { float t = ws[w]; ws[w] = s; s += t; }
    }
    __syncthreads();
    gc[idx] = v + ws[warp];
}

// ---------------- tensor-core S_in ----------------
#define SIN_KS_F   0
#define SIN_VS_F   (32*132)
#define SIN_KTH_B  (2*32*132*4)
#define SIN_KTL_B  (SIN_KTH_B + 128*40*2)
#define SIN_VTH_B  (SIN_KTL_B + 128*40*2)
#define SIN_VTL_B  (SIN_VTH_B + 128*40*2)
#define SIN_SMEM   (SIN_VTL_B + 128*40*2)

__global__ __launch_bounds__(256) void sin_tc_kernel(
    const float* __restrict__ k, const float* __restrict__ v,
    const float* __restrict__ gc, float* __restrict__ Sin)
{
    extern __shared__ __align__(16) char smc[];
    float* Ks = (float*)smc;
    float* Vs = (float*)smc + SIN_VS_F;
    __nv_bfloat162* KTh = (__nv_bfloat162*)(smc + SIN_KTH_B);
    __nv_bfloat162* KTl = (__nv_bfloat162*)(smc + SIN_KTL_B);
    __nv_bfloat162* VTh = (__nv_bfloat162*)(smc + SIN_VTH_B);
    __nv_bfloat162* VTl = (__nv_bfloat162*)(smc + SIN_VTL_B);
    __shared__ float kd[32];
    const uint32_t smb = smem_u32(smc);

    int blk = blockIdx.x;
    int n = blk & 15, h = (blk >> 4) & 15, b = blk >> 8;
    int tid = threadIdx.x, lane = tid & 31, wid = tid >> 5;
    int wm = wid >> 2, wn = wid & 3;
    const float* gcc = gc + ((size_t)(b * H_ + h)) * T_ + n * CH_;
    float gtot = gcc[CH_ - 1];
    int rowbase = b * T_ + n * CH_;

    uint32_t aoff[4];
#pragma unroll
    for (int mt = 0; mt < 4; mt++)
        aoff[mt] = (uint32_t)((wm * 64 + mt * 16 + (lane & 15)) * 80 + ((lane >> 4) << 4));
    uint32_t boff[2];
    {
        int q = lane >> 3, r = lane & 7;
#pragma unroll
        for (int np = 0; np < 2; np++) {
            int nr = wn * 32 + np * 16 + ((q >> 1) << 3) + r;
            boff[np] = (uint32_t)(nr * 80 + ((q & 1) << 4));
        }
    }

    float acc[4][4][4];
#pragma unroll
    for (int i = 0; i < 4; i++)
#pragma unroll
        for (int j = 0; j < 4; j++)
#pragma unroll
            for (int e = 0; e < 4; e++) acc[i][j][e] = 0.f;

    int d = tid & 127, sh = tid >> 7;

    for (int slab = 0; slab < 8; slab++) {
        int s_base = slab * 32;
        if (tid < 32) kd[tid] = expf(gtot - gcc[s_base + tid]) * SCALE_;
#pragma unroll
        for (int l = 0; l < 4; l++) {
            int li = tid + l * 256;
            int c = li >> 5, gcol = (li & 31) << 2;
            size_t gi = ((size_t)(rowbase + s_base + c)) * D_ + h * HD_ + gcol;
            *(float4*)&Ks[c * 132 + gcol] = *(const float4*)&k[gi];
            *(float4*)&Vs[c * 132 + gcol] = *(const float4*)&v[gi];
        }
        __syncthreads();

#pragma unroll
        for (int j = 0; j < 8; j++) {
            int s0 = sh * 16 + 2 * j;
            float ka = Ks[s0 * 132 + d] * kd[s0];
            float kb = Ks[(s0 + 1) * 132 + d] * kd[s0 + 1];
            float va = Vs[s0 * 132 + d];
            float vb = Vs[(s0 + 1) * 132 + d];
            int oi = d * 20 + sh * 8 + j;
            KTh[oi] = hi2_of(ka, kb);
            KTl[oi] = lo2_of(ka, kb);
            VTh[oi] = hi2_of(va, vb);
            VTl[oi] = lo2_of(va, vb);
        }
        __syncthreads();

#pragma unroll
        for (int pass = 0; pass < 3; pass++) {
            uint32_t Ab = smb + ((pass == 1) ? SIN_KTL_B : SIN_KTH_B);
            uint32_t Bb = smb + ((pass == 2) ? SIN_VTL_B : SIN_VTH_B);
#pragma unroll
            for (int ks = 0; ks < 2; ks++) {
                uint32_t fa[4][4], fb[2][4];
#pragma unroll
                for (int mt = 0; mt < 4; mt++) ldmat4(fa[mt], Ab + aoff[mt] + ks * 32);
#pragma unroll
                for (int np = 0; np < 2; np++) ldmat4(fb[np], Bb + boff[np] + ks * 32);
#pragma unroll
                for (int mt = 0; mt < 4; mt++)
#pragma unroll
                    for (int nt = 0; nt < 4; nt++)
                        mma_bf16(acc[mt][nt], fa[mt],
                                 fb[nt >> 1][(nt & 1) * 2], fb[nt >> 1][(nt & 1) * 2 + 1]);
            }
        }
        __syncthreads();
    }

    size_t base = (size_t)blk * (HD_ * HD_);
    int tq = lane >> 2, tr = lane & 3;
#pragma unroll
    for (int mt = 0; mt < 4; mt++) {
#pragma unroll
        for (int nt = 0; nt < 4; nt++) {
            int m = wm * 64 + mt * 16 + tq;
            int nn = wn * 32 + nt * 8 + tr * 2;
            *(float2*)&Sin[base + (size_t)m * HD_ + nn]       = make_float2(acc[mt][nt][0], acc[mt][nt][1]);
            *(float2*)&Sin[base + (size_t)(m + 8) * HD_ + nn] = make_float2(acc[mt][nt][2], acc[mt][nt][3]);
        }
    }
}

__global__ __launch_bounds__(256) void scan_kernel(
    const float* __restrict__ Sin, const float* __restrict__ gc, float* __restrict__ Spre)
{
    int blk = blockIdx.x;
    int bh = blk >> 3, part = blk & 7;
    int e0 = part * 2048 + threadIdx.x;
    float S[8];
#pragma unroll
    for (int l = 0; l < 8; l++) S[l] = 0.f;
    for (int n = 0; n < NCH_; n++) {
        float cd = expf(gc[(size_t)bh * T_ + n * CH_ + (CH_ - 1)]);
        size_t base = ((size_t)(bh * NCH_ + n)) * (HD_ * HD_);
#pragma unroll
        for (int l = 0; l < 8; l++) {
            int idx = e0 + l * 256;
            Spre[base + idx] = S[l];
            S[l] = S[l] * cd + Sin[base + idx];
        }
    }
}

// ============================= tensor-core out =============================
// Per block: 128-row tile of one (b,h,n) chunk. acc O[128x128] via mma.sync.
// Row strides: Q/K/SP tiles 136 bf16 = 68 bf162 = 272 B; P/VT tiles 72 bf16 = 36 bf162 = 144 B.
#define OQH_B  0
#define OQL_B  34816
#define OKH_B  69632
#define OKL_B  87040
#define OPH_B  104448
#define OPL_B  122880
#define OVS_B  141312
#define OVTH_B 175104
#define OVTL_B 193536
#define OUT_SMEM 211968

__global__ void __launch_bounds__(256, 1) out_tc_kernel(
    const float* __restrict__ q, const float* __restrict__ k,
    const float* __restrict__ v, const float* __restrict__ g,
    const float* __restrict__ gc, const float* __restrict__ Spre,
    __nv_bfloat16* __restrict__ ohi, __nv_bfloat16* __restrict__ olo)
{
    extern __shared__ __align__(16) char smo[];
    __nv_bfloat162* QH  = (__nv_bfloat162*)(smo + OQH_B);
    __nv_bfloat162* QL  = (__nv_bfloat162*)(smo + OQL_B);
    __nv_bfloat162* KH  = (__nv_bfloat162*)(smo + OKH_B);
    __nv_bfloat162* KL  = (__nv_bfloat162*)(smo + OKL_B);
    __nv_bfloat162* PH  = (__nv_bfloat162*)(smo + OPH_B);
    __nv_bfloat162* PL  = (__nv_bfloat162*)(smo + OPL_B);
    __nv_bfloat162* SPH = (__nv_bfloat162*)(smo + OKH_B);   // SpT hi (overlaps K)
    __nv_bfloat162* SPL = (__nv_bfloat162*)(smo + OPH_B);   // SpT lo (overlaps P)
    float* VS = (float*)(smo + OVS_B);
    __nv_bfloat162* VTH = (__nv_bfloat162*)(smo + OVTH_B);
    __nv_bfloat162* VTL = (__nv_bfloat162*)(smo + OVTL_B);
    __shared__ float gq[128], gk[64], redo[128][4];
    const uint32_t smb = smem_u32(smo);

    int blk = blockIdx.x;
    int rt = blk & 1, n = (blk >> 1) & 15, h = (blk >> 5) & 15, b = blk >> 9;
    int tid = threadIdx.x, lane = tid & 31, wid = tid >> 5;
    int wm = wid >> 2, wn = wid & 3;          // 2 x 4, warp tile 64 x 32
    int tq = lane >> 2, tr = lane & 3;
    int c0 = rt * 128;
    int rowbase = b * T_ + n * CH_;
    const float* gcc = gc + ((size_t)(b * H_ + h)) * T_ + n * CH_;
    size_t sbase = ((size_t)(blk >> 1)) * (HD_ * HD_);

    uint32_t aQ[4], aP[4];
#pragma unroll
    for (int mt = 0; mt < 4; mt++) {
        int mr = wm * 64 + mt * 16 + (lane & 15);
        aQ[mt] = (uint32_t)(mr * 272 + ((lane >> 4) << 4));
        aP[mt] = (uint32_t)(mr * 144 + ((lane >> 4) << 4));
    }
    int qq = lane >> 3, qr = lane & 7;
    uint32_t b1, bX[2], b2[2];
    b1 = (uint32_t)((wn * 16 + ((qq >> 1) << 3) + qr) * 272 + ((qq & 1) << 4));
#pragma unroll
    for (int np = 0; np < 2; np++) {
        int nr = wn * 32 + np * 16 + ((qq >> 1) << 3) + qr;
        bX[np] = (uint32_t)(nr * 272 + ((qq & 1) << 4));
        b2[np] = (uint32_t)(nr * 144 + ((qq & 1) << 4));
    }

    float acc[4][4][4];
#pragma unroll
    for (int i = 0; i < 4; i++)
#pragma unroll
        for (int j = 0; j < 4; j++)
#pragma unroll
            for (int e = 0; e < 4; e++) acc[i][j][e] = 0.f;

    if (tid < 128) gq[tid] = gcc[c0 + tid];
    __syncthreads();

    // ---- Phase C: Qd hi/lo (68 bf162 per row) ----
#pragma unroll
    for (int l = 0; l < 16; l++) {
        int li = tid + l * 256;
        int row = li >> 5, col = (li & 31) << 2;
        float4 qv = *(const float4*)&q[((size_t)(rowbase + c0 + row)) * D_ + h * HD_ + col];
        float s = expf(gq[row]);
        qv.x *= s; qv.y *= s; qv.z *= s; qv.w *= s;
        int oi = row * 68 + (col >> 1);
        QH[oi] = hi2_of(qv.x, qv.y); QH[oi + 1] = hi2_of(qv.z, qv.w);
        QL[oi] = lo2_of(qv.x, qv.y); QL[oi + 1] = lo2_of(qv.z, qv.w);
    }
    // Spre transpose+split: 4 slabs of 32 d-rows; SP rows 68 bf162
    int te = tid & 127, th = tid >> 7;
    for (int sl = 0; sl < 4; sl++) {
        __syncthreads();
#pragma unroll
        for (int l = 0; l < 4; l++) {
            int li = tid + l * 256;
            int dr = li >> 5, col = (li & 31) << 2;
            *(float4*)&VS[dr * 132 + col] = *(const float4*)&Spre[sbase + (size_t)(sl * 32 + dr) * HD_ + col];
        }
        __syncthreads();
#pragma unroll
        for (int j = 0; j < 8; j++) {
            int dl = th * 16 + 2 * j;
            float a = VS[dl * 132 + te], c = VS[(dl + 1) * 132 + te];
            int oi = te * 68 + sl * 16 + th * 8 + j;
            SPH[oi] = hi2_of(a, c);
            SPL[oi] = lo2_of(a, c);
        }
    }
    __syncthreads();
    // 3-pass cross GEMM: K=128 (8 ks)
#pragma unroll
    for (int pass = 0; pass < 3; pass++) {
        uint32_t Ab = smb + ((pass == 1) ? OQL_B : OQH_B);
        uint32_t Bb = smb + ((pass == 2) ? OPH_B : OKH_B);
#pragma unroll
        for (int ks = 0; ks < 8; ks++) {
            uint32_t fa[4][4], fb[2][4];
#pragma unroll
            for (int mt = 0; mt < 4; mt++) ldmat4(fa[mt], Ab + aQ[mt] + ks * 32);
#pragma unroll
            for (int np = 0; np < 2; np++) ldmat4(fb[np], Bb + bX[np] + ks * 32);
#pragma unroll
            for (int mt = 0; mt < 4; mt++)
#pragma unroll
                for (int nt = 0; nt < 4; nt++)
                    mma_bf16(acc[mt][nt], fa[mt],
                             fb[nt >> 1][(nt & 1) * 2], fb[nt >> 1][(nt & 1) * 2 + 1]);
        }
    }
    __syncthreads();

    // reload plain Q hi/lo (overwrites Qd)
#pragma unroll
    for (int l = 0; l < 16; l++) {
        int li = tid + l * 256;
        int row = li >> 5, col = (li & 31) << 2;
        float4 qv = *(const float4*)&q[((size_t)(rowbase + c0 + row)) * D_ + h * HD_ + col];
        int oi = row * 68 + (col >> 1);
        QH[oi] = hi2_of(qv.x, qv.y); QH[oi + 1] = hi2_of(qv.z, qv.w);
        QL[oi] = lo2_of(qv.x, qv.y); QL[oi + 1] = lo2_of(qv.z, qv.w);
    }

    // ---- Phase S: causal slabs of 64 ----
    int nslab = 2 * (rt + 1);
    for (int st = 0; st < nslab; st++) {
        int s0 = st * 64;
        if (tid < 64) gk[tid] = gcc[s0 + tid];
        // K slab -> KH/KL (68 bf162 per row)
#pragma unroll
        for (int l = 0; l < 8; l++) {
            int li = tid + l * 256;
            int sr = li >> 5, col = (li & 31) << 2;
            float4 kv = *(const float4*)&k[((size_t)(rowbase + s0 + sr)) * D_ + h * HD_ + col];
            int oi = sr * 68 + (col >> 1);
            KH[oi] = hi2_of(kv.x, kv.y); KH[oi + 1] = hi2_of(kv.z, kv.w);
            KL[oi] = lo2_of(kv.x, kv.y); KL[oi + 1] = lo2_of(kv.z, kv.w);
        }
        __syncthreads();

        // GEMM1: scores (M=128, N=64, K=128), 3-pass
        float sacc[4][2][4];
#pragma unroll
        for (int i = 0; i < 4; i++)
#pragma unroll
            for (int j = 0; j < 2; j++)
#pragma unroll
                for (int e = 0; e < 4; e++) sacc[i][j][e] = 0.f;
#pragma unroll
        for (int pass = 0; pass < 3; pass++) {
            uint32_t Ab = smb + ((pass == 1) ? OQL_B : OQH_B);
            uint32_t Bb = smb + ((pass == 2) ? OKL_B : OKH_B);
#pragma unroll
            for (int ks = 0; ks < 8; ks++) {
                uint32_t fa[4][4], fb[4];
#pragma unroll
                for (int mt = 0; mt < 4; mt++) ldmat4(fa[mt], Ab + aQ[mt] + ks * 32);
                ldmat4(fb, Bb + b1 + ks * 32);
#pragma unroll
                for (int mt = 0; mt < 4; mt++)
#pragma unroll
                    for (int nt = 0; nt < 2; nt++)
                        mma_bf16(sacc[mt][nt], fa[mt], fb[nt * 2], fb[nt * 2 + 1]);
            }
        }

        // epilogue: P = mask * sacc * SCALE * exp(gq[m]-gk[s]); P rows 36 bf162
#pragma unroll
        for (int mt = 0; mt < 4; mt++) {
#pragma unroll
            for (int nt = 0; nt < 2; nt++) {
                int m = wm * 64 + mt * 16 + tq;
                int s = wn * 16 + nt * 8 + tr * 2;
                int rg0 = c0 + m, rg1 = c0 + m + 8;
                int sg0 = s0 + s, sg1 = s0 + s + 1;
                float p00 = (sg0 <= rg0) ? sacc[mt][nt][0] * SCALE_ * expf(gq[m] - gk[s])     : 0.f;
                float p01 = (sg1 <= rg0) ? sacc[mt][nt][1] * SCALE_ * expf(gq[m] - gk[s + 1]) : 0.f;
                float p10 = (sg0 <= rg1) ? sacc[mt][nt][2] * SCALE_ * expf(gq[m + 8] - gk[s])     : 0.f;
                float p11 = (sg1 <= rg1) ? sacc[mt][nt][3] * SCALE_ * expf(gq[m + 8] - gk[s + 1]) : 0.f;
                int oi0 = m * 36 + (s >> 1);
                int oi1 = (m + 8) * 36 + (s >> 1);
                PH[oi0] = hi2_of(p00, p01); PL[oi0] = lo2_of(p00, p01);
                PH[oi1] = hi2_of(p10, p11); PL[oi1] = lo2_of(p10, p11);
            }
        }
        // V slab fp32 stage
#pragma unroll
        for (int l = 0; l < 8; l++) {
            int li = tid + l * 256;
            int sr = li >> 5, col = (li & 31) << 2;
            *(float4*)&VS[sr * 132 + col] = *(const float4*)&v[((size_t)(rowbase + s0 + sr)) * D_ + h * HD_ + col];
        }
        __syncthreads();
        // V transpose+split: VT[e][s], rows 36 bf162
#pragma unroll
        for (int j = 0; j < 16; j++) {
            int sl = th * 32 + 2 * j;
            float a = VS[sl * 132 + te], c = VS[(sl + 1) * 132 + te];
            int oi = te * 36 + th * 16 + j;
            VTH[oi] = hi2_of(a, c);
            VTL[oi] = lo2_of(a, c);
        }
        __syncthreads();

        // GEMM2: O += P @ V (M=128, N=128, K=64), 3-pass
#pragma unroll
        for (int pass = 0; pass < 3; pass++) {
            uint32_t Ab = smb + ((pass == 1) ? OPL_B : OPH_B);
            uint32_t Bb = smb + ((pass == 2) ? OVTL_B : OVTH_B);
#pragma unroll
            for (int ks = 0; ks < 4; ks++) {
                uint32_t fa[4][4], fb[2][4];
#pragma unroll
                for (int mt = 0; mt < 4; mt++) ldmat4(fa[mt], Ab + aP[mt] + ks * 32);
#pragma unroll
                for (int np = 0; np < 2; np++) ldmat4(fb[np], Bb + b2[np] + ks * 32);
#pragma unroll
                for (int mt = 0; mt < 4; mt++)
#pragma unroll
                    for (int nt = 0; nt < 4; nt++)
                        mma_bf16(acc[mt][nt], fa[mt],
                                 fb[nt >> 1][(nt & 1) * 2], fb[nt >> 1][(nt & 1) * 2 + 1]);
            }
        }
        __syncthreads();
    }

    // ---- Phase E: RMS + SiLU gate + hi/lo store ----
#pragma unroll
    for (int mt = 0; mt < 4; mt++) {
        float s0v = 0.f, s1v = 0.f;
#pragma unroll
        for (int nt = 0; nt < 4; nt++) {
            s0v += acc[mt][nt][0] * acc[mt][nt][0] + acc[mt][nt][1] * acc[mt][nt][1];
            s1v += acc[mt][nt][2] * acc[mt][nt][2] + acc[mt][nt][3] * acc[mt][nt][3];
        }
        s0v += __shfl_xor_sync(0xffffffffu, s0v, 1);
        s0v += __shfl_xor_sync(0xffffffffu, s0v, 2);
        s1v += __shfl_xor_sync(0xffffffffu, s1v, 1);
        s1v += __shfl_xor_sync(0xffffffffu, s1v, 2);
        if (tr == 0) {
            redo[wm * 64 + mt * 16 + tq][wn]     = s0v;
            redo[wm * 64 + mt * 16 + tq + 8][wn] = s1v;
        }
    }
    __syncthreads();
#pragma unroll
    for (int mt = 0; mt < 4; mt++) {
        int m = wm * 64 + mt * 16 + tq;
        float r0 = redo[m][0] + redo[m][1] + redo[m][2] + redo[m][3];
        float r1 = redo[m + 8][0] + redo[m + 8][1] + redo[m + 8][2] + redo[m + 8][3];
        float rn0 = rsqrtf(r0 * (1.0f / 128.0f) + 1e-5f);
        float rn1 = rsqrtf(r1 * (1.0f / 128.0f) + 1e-5f);
#pragma unroll
        for (int nt = 0; nt < 4; nt++) {
            int e = wn * 32 + nt * 8 + tr * 2;
            size_t gi0 = ((size_t)(rowbase + c0 + m)) * D_ + h * HD_ + e;
            size_t gi1 = ((size_t)(rowbase + c0 + m + 8)) * D_ + h * HD_ + e;
            float2 g0 = *(const float2*)&g[gi0];
            float2 g1 = *(const float2*)&g[gi1];
            float o00 = acc[mt][nt][0] * rn0 * (g0.x / (1.f + expf(-g0.x)));
            float o01 = acc[mt][nt][1] * rn0 * (g0.y / (1.f + expf(-g0.y)));
            float o10 = acc[mt][nt][2] * rn1 * (g1.x / (1.f + expf(-g1.x)));
            float o11 = acc[mt][nt][3] * rn1 * (g1.y / (1.f + expf(-g1.y)));
            *(__nv_bfloat162*)&ohi[gi0] = hi2_of(o00, o01);
            *(__nv_bfloat162*)&olo[gi0] = lo2_of(o00, o01);
            *(__nv_bfloat162*)&ohi[gi1] = hi2_of(o10, o11);
            *(__nv_bfloat162*)&olo[gi1] = lo2_of(o10, o11);
        }
    }
}

// ============================= launcher =============================
extern "C" void kernel_launch(void* const* d_in, const int* in_sizes, int n_in,
                              void* d_out, int out_size)
{
    const float* x    = (const float*)d_in[0];
    const float* cosb = (const float*)d_in[1];
    const float* sinb = (const float*)d_in[2];
    const float* Wq   = (const float*)d_in[3];
    const float* Wk   = (const float*)d_in[4];
    const float* Wv   = (const float*)d_in[5];
    const float* Wg   = (const float*)d_in[6];
    const float* Wgt  = (const float*)d_in[7];
    const float* Wout = (const float*)d_in[8];
    float* out = (float*)d_out;

    float *q, *k, *v, *g, *gt, *gc, *sbuf, *spre;
    __nv_bfloat16 *xhi, *xlo, *ohi, *olo, *wthi, *wtlo;
    cudaGetSymbolAddress((void**)&q,    g_q);
    cudaGetSymbolAddress((void**)&k,    g_k);
    cudaGetSymbolAddress((void**)&v,    g_v);
    cudaGetSymbolAddress((void**)&g,    g_g);
    cudaGetSymbolAddress((void**)&gt,   g_gt);
    cudaGetSymbolAddress((void**)&gc,   g_gc);
    cudaGetSymbolAddress((void**)&sbuf, g_sinbuf);
    cudaGetSymbolAddress((void**)&spre, g_sprebuf);
    cudaGetSymbolAddress((void**)&xhi,  g_xhi);
    cudaGetSymbolAddress((void**)&xlo,  g_xlo);
    cudaGetSymbolAddress((void**)&ohi,  g_ohi);
    cudaGetSymbolAddress((void**)&olo,  g_olo);
    cudaGetSymbolAddress((void**)&wthi, g_wthi);
    cudaGetSymbolAddress((void**)&wtlo, g_wtlo);

    cudaFuncSetAttribute(tc_gemm, cudaFuncAttributeMaxDynamicSharedMemorySize, TCG_SMEM);
    cudaFuncSetAttribute(sin_tc_kernel, cudaFuncAttributeMaxDynamicSharedMemorySize, SIN_SMEM);
    cudaFuncSetAttribute(out_tc_kernel, cudaFuncAttributeMaxDynamicSharedMemorySize, OUT_SMEM);

    const size_t WSZ = (size_t)D_ * D_;
    dim3 wgrid(D_ / 32, D_ / 32, 5);
    dim3 ggrid4(D_ / 128, BT_ / 128, 4);
    dim3 ggrid1(D_ / 128, BT_ / 128, 1);

    wsplit_all<<<wgrid, 256>>>(Wq, Wk, Wv, Wg, Wout, wthi, wtlo);
    split_kernel<<<(BT_ * (D_ / 4)) / 256, 256>>>(x, xhi, xlo);
    gt_kernel<<<BT_ / 4, 128>>>(x, Wgt, gt);
    cumsum_kernel<<<B_ * H_ * NCH_, 256>>>(gt, gc);
    tc_gemm<<<ggrid4, 128, TCG_SMEM>>>(xhi, xlo, wthi, wtlo, q, k, v, g, cosb, sinb);
    sin_tc_kernel<<<B_ * H_ * NCH_, 256, SIN_SMEM>>>(k, v, gc, sbuf);
    scan_kernel<<<B_ * H_ * 8, 256>>>(sbuf, gc, spre);
    out_tc_kernel<<<B_ * H_ * NCH_ * 2, 256, OUT_SMEM>>>(q, k, v, g, gc, spre, ohi, olo);
    tc_gemm<<<ggrid1, 128, TCG_SMEM>>>(ohi, olo, wthi + 4 * WSZ, wtlo + 4 * WSZ,
                                       out, out, out, out, nullptr, nullptr);
}